// round 1
// baseline (speedup 1.0000x reference)
#include <cuda_runtime.h>

#define DIM 8192

// XOR swizzle on low-5 bits: conflict-free smem for all structured layouts.
__device__ __forceinline__ int phys(int i) {
    return (i & ~31) | ((i ^ (i >> 5)) & 31);
}

// Apply 2x2 complex gate to register pairs differing in register-bit BQ.
template<int BQ>
__device__ __forceinline__ void rot_regs(float (&re)[32], float (&im)[32], const float (&g)[8]) {
#pragma unroll
    for (int k0 = 0; k0 < 32; k0++) {
        if (k0 & (1 << BQ)) continue;
        const int k1 = k0 | (1 << BQ);
        const float ar = re[k0], ai = im[k0], br = re[k1], bi = im[k1];
        re[k0] = g[0]*ar - g[1]*ai + g[2]*br - g[3]*bi;
        im[k0] = g[0]*ai + g[1]*ar + g[2]*bi + g[3]*br;
        re[k1] = g[4]*ar - g[5]*ai + g[6]*br - g[7]*bi;
        im[k1] = g[4]*ai + g[5]*ar + g[6]*bi + g[7]*br;
    }
}

__device__ __forceinline__ void load_gate(const float* gsm, float (&g)[8]) {
    const float4 a = *reinterpret_cast<const float4*>(gsm);
    const float4 b = *reinterpret_cast<const float4*>(gsm + 4);
    g[0]=a.x; g[1]=a.y; g[2]=a.z; g[3]=a.w;
    g[4]=b.x; g[5]=b.y; g[6]=b.z; g[7]=b.w;
}

__global__ void __launch_bounds__(256, 2)
qc_kernel(const float* __restrict__ x, const float* __restrict__ w,
          float* __restrict__ out)
{
    extern __shared__ float2 st[];                 // 8192 complex amps (64 KB)
    __shared__ __align__(16) float gates[26][8];   // 2 layers x 13 qubits x (U as 4 complex)
    __shared__ int   mk8[32];                      // M1(k << 8) for the layer-0 scatter
    __shared__ float red[8];

    const int tid = threadIdx.x;
    const int b   = blockIdx.x;

    // ---- gate matrices: Rot(phi,theta,omega) = RZ(om) RY(th) RZ(phi) ----
    if (tid < 26) {
        const int l = tid / 13, q = tid - l * 13;
        const float phi = w[l*39 + q*3 + 0];
        const float th  = w[l*39 + q*3 + 1];
        const float om  = w[l*39 + q*3 + 2];
        float s, c;   sincosf(0.5f * th, &s, &c);
        float sa, ca; sincosf(0.5f * (phi + om), &sa, &ca);
        float sd, cd; sincosf(0.5f * (phi - om), &sd, &cd);
        gates[tid][0] =  ca * c;  gates[tid][1] = -sa * c;   // U00
        gates[tid][2] = -cd * s;  gates[tid][3] = -sd * s;   // U01
        gates[tid][4] =  cd * s;  gates[tid][5] = -sd * s;   // U10
        gates[tid][6] =  ca * c;  gates[tid][7] =  sa * c;   // U11
    }

    // Layer-0 CNOT chain (r=1) as GF(2) map in BIT space (qubit q <-> bit 12-q):
    // bit_t(j) = parity(ROWS1[t] & i)
    const int ROWS1[13] = {8191,8190,8188,8184,8176,8160,8128,8064,
                           7936,7680,7168,6144,4095};
    if (tid < 32) {
        const int i = tid << 8;
        int j = 0;
#pragma unroll
        for (int t = 0; t < 13; t++) j |= (__popc(ROWS1[t] & i) & 1) << t;
        mk8[tid] = j;
    }
    int mtid = 0;
#pragma unroll
    for (int t = 0; t < 13; t++) mtid |= (__popc(ROWS1[t] & tid) & 1) << t;

    // ---- load row, normalize (amplitude embedding) ----
    float re[32], im[32];
    const float4* xp = reinterpret_cast<const float4*>(x + (size_t)b * DIM + tid * 32);
    float ss = 0.f;
#pragma unroll
    for (int k4 = 0; k4 < 8; k4++) {
        const float4 v = xp[k4];
        re[k4*4+0]=v.x; re[k4*4+1]=v.y; re[k4*4+2]=v.z; re[k4*4+3]=v.w;
        ss += v.x*v.x + v.y*v.y + v.z*v.z + v.w*v.w;
    }
#pragma unroll
    for (int o = 16; o > 0; o >>= 1) ss += __shfl_xor_sync(0xffffffffu, ss, o);
    if ((tid & 31) == 0) red[tid >> 5] = ss;
    __syncthreads();
    const float inv = rsqrtf(red[0]+red[1]+red[2]+red[3]+red[4]+red[5]+red[6]+red[7]);
#pragma unroll
    for (int k = 0; k < 32; k++) { re[k] *= inv; im[k] = 0.f; }

    float g[8];
#pragma unroll 1
    for (int l = 0; l < 2; l++) {
        const int gb = l * 13;
        // pass A: reg index = state bits 0-4  <->  qubits 12..8
        load_gate(gates[gb + 12], g); rot_regs<0>(re, im, g);
        load_gate(gates[gb + 11], g); rot_regs<1>(re, im, g);
        load_gate(gates[gb + 10], g); rot_regs<2>(re, im, g);
        load_gate(gates[gb +  9], g); rot_regs<3>(re, im, g);
        load_gate(gates[gb +  8], g); rot_regs<4>(re, im, g);
        // exchange A -> B
#pragma unroll
        for (int k = 0; k < 32; k++)
            st[phys((tid << 5) | k)] = make_float2(re[k], im[k]);
        __syncthreads();
#pragma unroll
        for (int k = 0; k < 32; k++) {
            const int i = ((tid >> 5) << 10) | (k << 5) | (tid & 31);
            const float2 v = st[phys(i)];
            re[k] = v.x; im[k] = v.y;
        }
        // pass B: reg index = state bits 5-9  <->  qubits 7..3
        load_gate(gates[gb + 7], g); rot_regs<0>(re, im, g);
        load_gate(gates[gb + 6], g); rot_regs<1>(re, im, g);
        load_gate(gates[gb + 5], g); rot_regs<2>(re, im, g);
        load_gate(gates[gb + 4], g); rot_regs<3>(re, im, g);
        load_gate(gates[gb + 3], g); rot_regs<4>(re, im, g);
        // exchange B -> C
#pragma unroll
        for (int k = 0; k < 32; k++) {
            const int i = ((tid >> 5) << 10) | (k << 5) | (tid & 31);
            st[phys(i)] = make_float2(re[k], im[k]);
        }
        __syncthreads();
#pragma unroll
        for (int k = 0; k < 32; k++) {
            const float2 v = st[phys((k << 8) | tid)];
            re[k] = v.x; im[k] = v.y;
        }
        // pass C: reg bits 2-4 = state bits 10-12  <->  qubits 2,1,0
        load_gate(gates[gb + 2], g); rot_regs<2>(re, im, g);
        load_gate(gates[gb + 1], g); rot_regs<3>(re, im, g);
        load_gate(gates[gb + 0], g); rot_regs<4>(re, im, g);

        if (l == 0) {
            // layer-0's 13 CNOTs as ONE scatter: new[M1(i)] = old[i]
            __syncthreads();
#pragma unroll
            for (int k = 0; k < 32; k++) {
                const int j = mk8[k] ^ mtid;
                st[phys(j)] = make_float2(re[k], im[k]);
            }
            __syncthreads();
#pragma unroll
            for (int k = 0; k < 32; k++) {
                const float2 v = st[phys((tid << 5) | k)];
                re[k] = v.x; im[k] = v.y;
            }
        }
    }

    // ---- measurement: layer-1 CNOT map folded into the sign ----
    // final bit6 = parity(i & 5440); i = (k<<8)|tid  ->  k-mask 21, tid-bit 64
    float acc = 0.f;
#pragma unroll
    for (int k = 0; k < 32; k++) {
        const float p = re[k]*re[k] + im[k]*im[k];
        acc += (__popc(k & 21) & 1) ? -p : p;
    }
    if (tid & 64) acc = -acc;
#pragma unroll
    for (int o = 16; o > 0; o >>= 1) acc += __shfl_xor_sync(0xffffffffu, acc, o);
    if ((tid & 31) == 0) red[tid >> 5] = acc;
    __syncthreads();
    if (tid == 0)
        out[b] = red[0]+red[1]+red[2]+red[3]+red[4]+red[5]+red[6]+red[7];
}

extern "C" void kernel_launch(void* const* d_in, const int* in_sizes, int n_in,
                              void* d_out, int out_size)
{
    const float* x = (const float*)d_in[0];
    const float* w = (const float*)d_in[1];
    float* out = (float*)d_out;
    const int B = in_sizes[0] / DIM;

    const size_t shmem = DIM * sizeof(float2);  // 64 KB
    cudaFuncSetAttribute(qc_kernel, cudaFuncAttributeMaxDynamicSharedMemorySize,
                         (int)shmem);
    qc_kernel<<<B, 256, shmem>>>(x, w, out);
}

// round 2
// speedup vs baseline: 1.1153x; 1.1153x over previous
#include <cuda_runtime.h>

#define DIM 8192
typedef unsigned long long u64;

// ---- packed f32x2 helpers (SASS FFMA2 path, PTX-only) ----
__device__ __forceinline__ float2 f2fma(float2 a, float2 b, float2 c) {
    u64 r, au = *(u64*)&a, bu = *(u64*)&b, cu = *(u64*)&c;
    asm("fma.rn.f32x2 %0,%1,%2,%3;" : "=l"(r) : "l"(au), "l"(bu), "l"(cu));
    return *(float2*)&r;
}
__device__ __forceinline__ float2 f2mul(float2 a, float2 b) {
    u64 r, au = *(u64*)&a, bu = *(u64*)&b;
    asm("mul.rn.f32x2 %0,%1,%2;" : "=l"(r) : "l"(au), "l"(bu));
    return *(float2*)&r;
}
__device__ __forceinline__ float2 f2add(float2 a, float2 b) {
    u64 r, au = *(u64*)&a, bu = *(u64*)&b;
    asm("add.rn.f32x2 %0,%1,%2;" : "=l"(r) : "l"(au), "l"(bu));
    return *(float2*)&r;
}

// XOR swizzle on low-5 bits: conflict-free smem for all structured layouts.
__device__ __forceinline__ int phys(int i) {
    return (i & ~31) | ((i ^ (i >> 5)) & 31);
}

// Apply 2x2 complex gate (packed over 2 batch rows) to register pairs
// differing in register-bit BQ.  g: [0..7]=g0..g7, [8]=-g1, [9]=-g3, [10]=-g5, [11]=-g7
template<int BQ>
__device__ __forceinline__ void rot2(float2 (&re)[32], float2 (&im)[32], const float2 (&g)[12]) {
#pragma unroll
    for (int k0 = 0; k0 < 32; k0++) {
        if (k0 & (1 << BQ)) continue;
        const int k1 = k0 | (1 << BQ);
        const float2 ar = re[k0], ai = im[k0], br = re[k1], bi = im[k1];
        re[k0] = f2fma(g[0], ar, f2fma(g[8],  ai, f2fma(g[2], br, f2mul(g[9],  bi))));
        im[k0] = f2fma(g[1], ar, f2fma(g[0],  ai, f2fma(g[3], br, f2mul(g[2],  bi))));
        re[k1] = f2fma(g[4], ar, f2fma(g[10], ai, f2fma(g[6], br, f2mul(g[11], bi))));
        im[k1] = f2fma(g[5], ar, f2fma(g[4],  ai, f2fma(g[7], br, f2mul(g[6],  bi))));
    }
}

__device__ __forceinline__ void load_gate(const float2* gsm, float2 (&g)[12]) {
#pragma unroll
    for (int j = 0; j < 12; j++) g[j] = gsm[j];
}

__global__ void __launch_bounds__(256, 1)
qc_kernel(const float* __restrict__ x, const float* __restrict__ w,
          float* __restrict__ out)
{
    extern __shared__ float4 st[];                 // 8192 x (re-pack, im-pack) = 128 KB
    __shared__ __align__(16) float2 gp[26][12];    // duplicated (+negated) gate coeffs
    __shared__ int    mk8[32];
    __shared__ float2 red[8];

    const int tid = threadIdx.x;
    const int b   = blockIdx.x;                    // handles batch rows 2b, 2b+1

    // ---- gate matrices: Rot(phi,theta,omega) = RZ(om) RY(th) RZ(phi) ----
    if (tid < 26) {
        const int l = tid / 13, q = tid - l * 13;
        const float phi = w[l*39 + q*3 + 0];
        const float th  = w[l*39 + q*3 + 1];
        const float om  = w[l*39 + q*3 + 2];
        float s, c;   sincosf(0.5f * th, &s, &c);
        float sa, ca; sincosf(0.5f * (phi + om), &sa, &ca);
        float sd, cd; sincosf(0.5f * (phi - om), &sd, &cd);
        const float g0 =  ca * c, g1 = -sa * c;    // U00
        const float g2 = -cd * s, g3 = -sd * s;    // U01
        const float g4 =  cd * s, g5 = -sd * s;    // U10
        const float g6 =  ca * c, g7 =  sa * c;    // U11
        gp[tid][0]  = make_float2( g0,  g0);
        gp[tid][1]  = make_float2( g1,  g1);
        gp[tid][2]  = make_float2( g2,  g2);
        gp[tid][3]  = make_float2( g3,  g3);
        gp[tid][4]  = make_float2( g4,  g4);
        gp[tid][5]  = make_float2( g5,  g5);
        gp[tid][6]  = make_float2( g6,  g6);
        gp[tid][7]  = make_float2( g7,  g7);
        gp[tid][8]  = make_float2(-g1, -g1);
        gp[tid][9]  = make_float2(-g3, -g3);
        gp[tid][10] = make_float2(-g5, -g5);
        gp[tid][11] = make_float2(-g7, -g7);
    }

    // Layer-0 CNOT chain (r=1) as GF(2) map in BIT space (qubit q <-> bit 12-q)
    const int ROWS1[13] = {8191,8190,8188,8184,8176,8160,8128,8064,
                           7936,7680,7168,6144,4095};
    if (tid < 32) {
        const int i = tid << 8;
        int j = 0;
#pragma unroll
        for (int t = 0; t < 13; t++) j |= (__popc(ROWS1[t] & i) & 1) << t;
        mk8[tid] = j;
    }
    int mtid = 0;
#pragma unroll
    for (int t = 0; t < 13; t++) mtid |= (__popc(ROWS1[t] & tid) & 1) << t;

    // ---- load two rows, normalize each (amplitude embedding) ----
    float2 re[32], im[32];
    const float4* xp0 = reinterpret_cast<const float4*>(x + (size_t)(2*b)   * DIM + tid * 32);
    const float4* xp1 = reinterpret_cast<const float4*>(x + (size_t)(2*b+1) * DIM + tid * 32);
    float2 ss = make_float2(0.f, 0.f);
#pragma unroll
    for (int k4 = 0; k4 < 8; k4++) {
        const float4 v0 = xp0[k4];
        const float4 v1 = xp1[k4];
        re[k4*4+0] = make_float2(v0.x, v1.x);
        re[k4*4+1] = make_float2(v0.y, v1.y);
        re[k4*4+2] = make_float2(v0.z, v1.z);
        re[k4*4+3] = make_float2(v0.w, v1.w);
    }
#pragma unroll
    for (int k = 0; k < 32; k++) ss = f2fma(re[k], re[k], ss);
#pragma unroll
    for (int o = 16; o > 0; o >>= 1) {
        u64 sv = *(u64*)&ss;
        u64 ov = __shfl_xor_sync(0xffffffffu, sv, o);
        ss = f2add(ss, *(float2*)&ov);
    }
    if ((tid & 31) == 0) red[tid >> 5] = ss;
    __syncthreads();
    float2 tot = make_float2(0.f, 0.f);
#pragma unroll
    for (int r = 0; r < 8; r++) tot = f2add(tot, red[r]);
    const float2 inv = make_float2(rsqrtf(tot.x), rsqrtf(tot.y));
#pragma unroll
    for (int k = 0; k < 32; k++) { re[k] = f2mul(re[k], inv); im[k] = make_float2(0.f, 0.f); }

    float2 g[12];
#pragma unroll 1
    for (int l = 0; l < 2; l++) {
        const int gb = l * 13;
        // pass A: reg index = state bits 0-4  <->  qubits 12..8
        load_gate(gp[gb + 12], g); rot2<0>(re, im, g);
        load_gate(gp[gb + 11], g); rot2<1>(re, im, g);
        load_gate(gp[gb + 10], g); rot2<2>(re, im, g);
        load_gate(gp[gb +  9], g); rot2<3>(re, im, g);
        load_gate(gp[gb +  8], g); rot2<4>(re, im, g);
        // exchange A -> B
#pragma unroll
        for (int k = 0; k < 32; k++)
            st[phys((tid << 5) | k)] = make_float4(re[k].x, re[k].y, im[k].x, im[k].y);
        __syncthreads();
#pragma unroll
        for (int k = 0; k < 32; k++) {
            const int i = ((tid >> 5) << 10) | (k << 5) | (tid & 31);
            const float4 v = st[phys(i)];
            re[k] = make_float2(v.x, v.y); im[k] = make_float2(v.z, v.w);
        }
        // pass B: reg index = state bits 5-9  <->  qubits 7..3
        load_gate(gp[gb + 7], g); rot2<0>(re, im, g);
        load_gate(gp[gb + 6], g); rot2<1>(re, im, g);
        load_gate(gp[gb + 5], g); rot2<2>(re, im, g);
        load_gate(gp[gb + 4], g); rot2<3>(re, im, g);
        load_gate(gp[gb + 3], g); rot2<4>(re, im, g);
        // exchange B -> C
        __syncthreads();
#pragma unroll
        for (int k = 0; k < 32; k++) {
            const int i = ((tid >> 5) << 10) | (k << 5) | (tid & 31);
            st[phys(i)] = make_float4(re[k].x, re[k].y, im[k].x, im[k].y);
        }
        __syncthreads();
#pragma unroll
        for (int k = 0; k < 32; k++) {
            const float4 v = st[phys((k << 8) | tid)];
            re[k] = make_float2(v.x, v.y); im[k] = make_float2(v.z, v.w);
        }
        // pass C: reg bits 2-4 = state bits 10-12  <->  qubits 2,1,0
        load_gate(gp[gb + 2], g); rot2<2>(re, im, g);
        load_gate(gp[gb + 1], g); rot2<3>(re, im, g);
        load_gate(gp[gb + 0], g); rot2<4>(re, im, g);

        if (l == 0) {
            // layer-0's 13 CNOTs as ONE scatter: new[M1(i)] = old[i]
            __syncthreads();
#pragma unroll
            for (int k = 0; k < 32; k++) {
                const int j = mk8[k] ^ mtid;
                st[phys(j)] = make_float4(re[k].x, re[k].y, im[k].x, im[k].y);
            }
            __syncthreads();
#pragma unroll
            for (int k = 0; k < 32; k++) {
                const float4 v = st[phys((tid << 5) | k)];
                re[k] = make_float2(v.x, v.y); im[k] = make_float2(v.z, v.w);
            }
        }
    }

    // ---- measurement: layer-1 CNOT map folded into the sign ----
    // final bit6 = parity(i & 5440); i = (k<<8)|tid  ->  k-mask 21, tid-bit 64
    const float2 mn1 = make_float2(-1.f, -1.f);
    float2 acc = make_float2(0.f, 0.f);
#pragma unroll
    for (int k = 0; k < 32; k++) {
        const float2 p = f2fma(re[k], re[k], f2mul(im[k], im[k]));
        if (__popc(k & 21) & 1) acc = f2fma(p, mn1, acc);
        else                    acc = f2add(acc, p);
    }
    if (tid & 64) acc = f2mul(acc, mn1);
#pragma unroll
    for (int o = 16; o > 0; o >>= 1) {
        u64 av = *(u64*)&acc;
        u64 ov = __shfl_xor_sync(0xffffffffu, av, o);
        acc = f2add(acc, *(float2*)&ov);
    }
    __syncthreads();
    if ((tid & 31) == 0) red[tid >> 5] = acc;
    __syncthreads();
    if (tid == 0) {
        float2 t = make_float2(0.f, 0.f);
#pragma unroll
        for (int r = 0; r < 8; r++) t = f2add(t, red[r]);
        out[2*b]   = t.x;
        out[2*b+1] = t.y;
    }
}

extern "C" void kernel_launch(void* const* d_in, const int* in_sizes, int n_in,
                              void* d_out, int out_size)
{
    const float* x = (const float*)d_in[0];
    const float* w = (const float*)d_in[1];
    float* out = (float*)d_out;
    const int B2 = (in_sizes[0] / DIM) / 2;        // 2 batch rows per CTA

    const size_t shmem = DIM * sizeof(float4);     // 128 KB
    cudaFuncSetAttribute(qc_kernel, cudaFuncAttributeMaxDynamicSharedMemorySize,
                         (int)shmem);
    qc_kernel<<<B2, 256, shmem>>>(x, w, out);
}

// round 3
// speedup vs baseline: 1.3848x; 1.2416x over previous
#include <cuda_runtime.h>

#define DIM 8192
typedef unsigned long long u64;

// ---- packed f32x2 helpers (SASS FFMA2/FMUL2 path, PTX-only) ----
__device__ __forceinline__ float2 f2fma(float2 a, float2 b, float2 c) {
    u64 r, au = *(u64*)&a, bu = *(u64*)&b, cu = *(u64*)&c;
    asm("fma.rn.f32x2 %0,%1,%2,%3;" : "=l"(r) : "l"(au), "l"(bu), "l"(cu));
    return *(float2*)&r;
}
__device__ __forceinline__ float2 f2mul(float2 a, float2 b) {
    u64 r, au = *(u64*)&a, bu = *(u64*)&b;
    asm("mul.rn.f32x2 %0,%1,%2;" : "=l"(r) : "l"(au), "l"(bu));
    return *(float2*)&r;
}
__device__ __forceinline__ float2 f2add(float2 a, float2 b) {
    u64 r, au = *(u64*)&a, bu = *(u64*)&b;
    asm("add.rn.f32x2 %0,%1,%2;" : "=l"(r) : "l"(au), "l"(bu));
    return *(float2*)&r;
}

// XOR swizzle: conflict-free smem for all structured layouts used below.
__device__ __forceinline__ int phys(int i) {
    return i ^ ((i >> 4) & 15);
}

// Phase tables (same for every batch row): A0 (layer-0 phi diag, applied to real
// input) and D01 = B0(i) * A1(M0(i)) (layer-0 omega merged with layer-1 phi
// conjugated through the layer-0 CNOT permutation).
__device__ float2 g_t0[DIM];
__device__ float2 g_t1[DIM];

#define ROWS1_INIT {8191,8190,8188,8184,8176,8160,8128,8064,7936,7680,7168,6144,4095}

__global__ void qc_setup(const float* __restrict__ w) {
    const int i = blockIdx.x * blockDim.x + threadIdx.x;   // 0..8191
    const int ROWS1[13] = ROWS1_INIT;
    float a0 = 0.f, b0 = 0.f;
#pragma unroll
    for (int q = 0; q < 13; q++) {
        const float sgn = ((i >> (12 - q)) & 1) ? 0.5f : -0.5f;
        a0 += sgn * w[q*3 + 0];       // layer-0 phi
        b0 += sgn * w[q*3 + 2];       // layer-0 omega
    }
    int j = 0;
#pragma unroll
    for (int t = 0; t < 13; t++) j |= (__popc(ROWS1[t] & i) & 1) << t;
    float a1 = 0.f;
#pragma unroll
    for (int q = 0; q < 13; q++) {
        const float sgn = ((j >> (12 - q)) & 1) ? 0.5f : -0.5f;
        a1 += sgn * w[39 + q*3 + 0];  // layer-1 phi at permuted index
    }
    float c, s;
    sincosf(a0, &s, &c);      g_t0[i] = make_float2(c, s);
    sincosf(b0 + a1, &s, &c); g_t1[i] = make_float2(c, s);
}

// Real RY rotation on register-bit BQ (applied independently to re and im).
template<int BQ>
__device__ __forceinline__ void rotY(float2 (&re)[16], float2 (&im)[16],
                                     float2 c, float2 s, float2 ns) {
#pragma unroll
    for (int k0 = 0; k0 < 16; k0++) {
        if (k0 & (1 << BQ)) continue;
        const int k1 = k0 | (1 << BQ);
        const float2 r0 = re[k0], r1 = re[k1], i0 = im[k0], i1 = im[k1];
        re[k0] = f2fma(c, r0, f2mul(ns, r1));
        re[k1] = f2fma(s, r0, f2mul(c,  r1));
        im[k0] = f2fma(c, i0, f2mul(ns, i1));
        im[k1] = f2fma(s, i0, f2mul(c,  i1));
    }
}

__global__ void __launch_bounds__(512, 1)
qc_kernel(const float* __restrict__ x, const float* __restrict__ w,
          float* __restrict__ out)
{
    extern __shared__ float4 st[];                 // 8192 x (re-pack, im-pack) = 128 KB
    __shared__ float2 gc[26], gs[26], gns[26];     // RY coeffs, duplicated packed
    __shared__ int    mk9[16];
    __shared__ float2 red[16];

    const int t    = threadIdx.x;
    const int b    = blockIdx.x;                   // batch rows 2b, 2b+1
    const int lane = t & 31;
    const int warp = t >> 5;

    if (t < 26) {
        const int l = t / 13, q = t - l * 13;
        const float th = w[l*39 + q*3 + 1];
        float s, c; sincosf(0.5f * th, &s, &c);
        gc[t]  = make_float2( c,  c);
        gs[t]  = make_float2( s,  s);
        gns[t] = make_float2(-s, -s);
    }
    const int ROWS1[13] = ROWS1_INIT;
    if (t < 16) {
        const int i = t << 9;
        int j = 0;
#pragma unroll
        for (int tt = 0; tt < 13; tt++) j |= (__popc(ROWS1[tt] & i) & 1) << tt;
        mk9[t] = j;
    }
    int m0t = 0;
#pragma unroll
    for (int tt = 0; tt < 13; tt++) m0t |= (__popc(ROWS1[tt] & t) & 1) << tt;

    // ---- load two rows (layout A: i = (t<<4)|k), reduce sum-of-squares ----
    float2 re[16], im[16];
    const float4* xp0 = reinterpret_cast<const float4*>(x + (size_t)(2*b)   * DIM + (t << 4));
    const float4* xp1 = reinterpret_cast<const float4*>(x + (size_t)(2*b+1) * DIM + (t << 4));
    float2 ss = make_float2(0.f, 0.f);
#pragma unroll
    for (int k4 = 0; k4 < 4; k4++) {
        const float4 v0 = xp0[k4];
        const float4 v1 = xp1[k4];
        re[k4*4+0] = make_float2(v0.x, v1.x);
        re[k4*4+1] = make_float2(v0.y, v1.y);
        re[k4*4+2] = make_float2(v0.z, v1.z);
        re[k4*4+3] = make_float2(v0.w, v1.w);
    }
#pragma unroll
    for (int k = 0; k < 16; k++) ss = f2fma(re[k], re[k], ss);
#pragma unroll
    for (int o = 16; o > 0; o >>= 1) {
        u64 sv = *(u64*)&ss;
        u64 ov = __shfl_xor_sync(0xffffffffu, sv, o);
        ss = f2add(ss, *(float2*)&ov);
    }
    if (lane == 0) red[warp] = ss;
    __syncthreads();
    float2 tot = make_float2(0.f, 0.f);
#pragma unroll
    for (int r = 0; r < 16; r++) tot = f2add(tot, red[r]);
    const float2 inv = make_float2(rsqrtf(tot.x), rsqrtf(tot.y));

    // ---- A0: per-amp phase on the real normalized input ----
    const float4* t0p = reinterpret_cast<const float4*>(g_t0) + (t << 3);
#pragma unroll
    for (int kk = 0; kk < 8; kk++) {
        const float4 cs = __ldg(&t0p[kk]);
        const int k0 = 2*kk, k1 = 2*kk + 1;
        float2 xs = f2mul(re[k0], inv);
        re[k0] = f2mul(xs, make_float2(cs.x, cs.x));
        im[k0] = f2mul(xs, make_float2(cs.y, cs.y));
        xs = f2mul(re[k1], inv);
        re[k1] = f2mul(xs, make_float2(cs.z, cs.z));
        im[k1] = f2mul(xs, make_float2(cs.w, cs.w));
    }

    const int iB_base = ((t >> 4) << 8) | (t & 15);

#pragma unroll 1
    for (int l = 0; l < 2; l++) {
        const int gb = 13 * l;
        // pass A: reg bits 0-3 = i bits 0-3 (qubits 12,11,10,9)
        rotY<0>(re, im, gc[gb+12], gs[gb+12], gns[gb+12]);
        rotY<1>(re, im, gc[gb+11], gs[gb+11], gns[gb+11]);
        rotY<2>(re, im, gc[gb+10], gs[gb+10], gns[gb+10]);
        rotY<3>(re, im, gc[gb+ 9], gs[gb+ 9], gns[gb+ 9]);
        // shfl gate: i bit 8 = lane bit 4 (qubit 4), partner = lane^16
        {
            const float2 cg   = gc[gb + 4];
            const float2 sSel = (lane & 16) ? gs[gb + 4] : gns[gb + 4];
#pragma unroll
            for (int k = 0; k < 16; k++) {
                const u64 pr = __shfl_xor_sync(0xffffffffu, *(u64*)&re[k], 16);
                const u64 pi = __shfl_xor_sync(0xffffffffu, *(u64*)&im[k], 16);
                re[k] = f2fma(cg, re[k], f2mul(sSel, *(const float2*)&pr));
                im[k] = f2fma(cg, im[k], f2mul(sSel, *(const float2*)&pi));
            }
        }
        // exchange A -> B
        __syncthreads();
#pragma unroll
        for (int k = 0; k < 16; k++)
            st[phys((t << 4) | k)] = make_float4(re[k].x, re[k].y, im[k].x, im[k].y);
        __syncthreads();
#pragma unroll
        for (int k = 0; k < 16; k++) {
            const float4 v = st[phys(iB_base | (k << 4))];
            re[k] = make_float2(v.x, v.y); im[k] = make_float2(v.z, v.w);
        }
        // pass B: reg bits = i bits 4-7 (qubits 8,7,6,5)
        rotY<0>(re, im, gc[gb+8], gs[gb+8], gns[gb+8]);
        rotY<1>(re, im, gc[gb+7], gs[gb+7], gns[gb+7]);
        rotY<2>(re, im, gc[gb+6], gs[gb+6], gns[gb+6]);
        rotY<3>(re, im, gc[gb+5], gs[gb+5], gns[gb+5]);
        // exchange B -> C
        __syncthreads();
#pragma unroll
        for (int k = 0; k < 16; k++)
            st[phys(iB_base | (k << 4))] = make_float4(re[k].x, re[k].y, im[k].x, im[k].y);
        __syncthreads();
#pragma unroll
        for (int k = 0; k < 16; k++) {
            const float4 v = st[phys((k << 9) | t)];
            re[k] = make_float2(v.x, v.y); im[k] = make_float2(v.z, v.w);
        }
        // pass C: reg bits = i bits 9-12 (qubits 3,2,1,0)
        rotY<0>(re, im, gc[gb+3], gs[gb+3], gns[gb+3]);
        rotY<1>(re, im, gc[gb+2], gs[gb+2], gns[gb+2]);
        rotY<2>(re, im, gc[gb+1], gs[gb+1], gns[gb+1]);
        rotY<3>(re, im, gc[gb+0], gs[gb+0], gns[gb+0]);

        if (l == 0) {
            // D01 elementwise phase, then layer-0 CNOT permutation as one scatter
            __syncthreads();
#pragma unroll
            for (int k = 0; k < 16; k++) {
                const float2 cs = __ldg(&g_t1[(k << 9) | t]);
                const float2 cd = make_float2(cs.x, cs.x);
                const float2 sd = make_float2(cs.y, cs.y);
                const float2 nsd = make_float2(-cs.y, -cs.y);
                const float2 tr = f2fma(cd, re[k], f2mul(nsd, im[k]));
                const float2 ti = f2fma(sd, re[k], f2mul(cd,  im[k]));
                st[phys(mk9[k] ^ m0t)] = make_float4(tr.x, tr.y, ti.x, ti.y);
            }
            __syncthreads();
#pragma unroll
            for (int k = 0; k < 16; k++) {
                const float4 v = st[phys((t << 4) | k)];
                re[k] = make_float2(v.x, v.y); im[k] = make_float2(v.z, v.w);
            }
        }
    }

    // ---- measurement: layer-1 CNOT folded into sign mask 5440 ----
    // i = (k<<9)|t: k-mask (bits 12,10) = 10, t-mask (bits 8,6) = 320
    const float2 mn1 = make_float2(-1.f, -1.f);
    float2 acc = make_float2(0.f, 0.f);
#pragma unroll
    for (int k = 0; k < 16; k++) {
        const float2 p = f2fma(re[k], re[k], f2mul(im[k], im[k]));
        if (__popc(k & 10) & 1) acc = f2fma(p, mn1, acc);
        else                    acc = f2add(acc, p);
    }
    if (__popc(t & 320) & 1) acc = f2mul(acc, mn1);
#pragma unroll
    for (int o = 16; o > 0; o >>= 1) {
        u64 av = *(u64*)&acc;
        u64 ov = __shfl_xor_sync(0xffffffffu, av, o);
        acc = f2add(acc, *(float2*)&ov);
    }
    __syncthreads();
    if (lane == 0) red[warp] = acc;
    __syncthreads();
    if (t == 0) {
        float2 tt = make_float2(0.f, 0.f);
#pragma unroll
        for (int r = 0; r < 16; r++) tt = f2add(tt, red[r]);
        out[2*b]   = tt.x;
        out[2*b+1] = tt.y;
    }
}

extern "C" void kernel_launch(void* const* d_in, const int* in_sizes, int n_in,
                              void* d_out, int out_size)
{
    const float* x = (const float*)d_in[0];
    const float* w = (const float*)d_in[1];
    float* out = (float*)d_out;
    const int B2 = (in_sizes[0] / DIM) / 2;        // 2 batch rows per CTA

    qc_setup<<<DIM / 256, 256>>>(w);

    const size_t shmem = DIM * sizeof(float4);     // 128 KB
    cudaFuncSetAttribute(qc_kernel, cudaFuncAttributeMaxDynamicSharedMemorySize,
                         (int)shmem);
    qc_kernel<<<B2, 512, shmem>>>(x, w, out);
}

// round 4
// speedup vs baseline: 1.4795x; 1.0684x over previous
#include <cuda_runtime.h>

#define DIM 8192
typedef unsigned long long u64;

// ---- packed f32x2 helpers (SASS FFMA2/FMUL2 path, PTX-only) ----
__device__ __forceinline__ float2 f2fma(float2 a, float2 b, float2 c) {
    u64 r, au = *(u64*)&a, bu = *(u64*)&b, cu = *(u64*)&c;
    asm("fma.rn.f32x2 %0,%1,%2,%3;" : "=l"(r) : "l"(au), "l"(bu), "l"(cu));
    return *(float2*)&r;
}
__device__ __forceinline__ float2 f2mul(float2 a, float2 b) {
    u64 r, au = *(u64*)&a, bu = *(u64*)&b;
    asm("mul.rn.f32x2 %0,%1,%2;" : "=l"(r) : "l"(au), "l"(bu));
    return *(float2*)&r;
}
__device__ __forceinline__ float2 f2add(float2 a, float2 b) {
    u64 r, au = *(u64*)&a, bu = *(u64*)&b;
    asm("add.rn.f32x2 %0,%1,%2;" : "=l"(r) : "l"(au), "l"(bu));
    return *(float2*)&r;
}

// XOR swizzle: conflict-free smem for all structured layouts used below.
__device__ __forceinline__ int phys(int i) {
    return i ^ ((i >> 4) & 15);
}

// Phase tables (shared by all batch rows): A0 (layer-0 phi diag, applied to the
// real input) and D01 = B0(i)*A1(M0(i)) (layer-0 omega merged with layer-1 phi
// conjugated through the layer-0 CNOT permutation). Last diagonal is unit-modulus
// and invisible to |amp|^2 -> dropped.
__device__ float2 g_t0[DIM];
__device__ float2 g_t1[DIM];

#define ROWS1_INIT {8191,8190,8188,8184,8176,8160,8128,8064,7936,7680,7168,6144,4095}

__global__ void qc_setup(const float* __restrict__ w) {
    const int i = blockIdx.x * blockDim.x + threadIdx.x;   // 0..8191
    const int ROWS1[13] = ROWS1_INIT;
    float a0 = 0.f, b0 = 0.f;
#pragma unroll
    for (int q = 0; q < 13; q++) {
        const float sgn = ((i >> (12 - q)) & 1) ? 0.5f : -0.5f;
        a0 += sgn * w[q*3 + 0];       // layer-0 phi
        b0 += sgn * w[q*3 + 2];       // layer-0 omega
    }
    int j = 0;
#pragma unroll
    for (int t = 0; t < 13; t++) j |= (__popc(ROWS1[t] & i) & 1) << t;
    float a1 = 0.f;
#pragma unroll
    for (int q = 0; q < 13; q++) {
        const float sgn = ((j >> (12 - q)) & 1) ? 0.5f : -0.5f;
        a1 += sgn * w[39 + q*3 + 0];  // layer-1 phi at permuted index
    }
    float c, s;
    sincosf(a0, &s, &c);      g_t0[i] = make_float2(c, s);
    sincosf(b0 + a1, &s, &c); g_t1[i] = make_float2(c, s);
}

// Real RY rotation on register-bit BQ (applied independently to re and im).
template<int BQ>
__device__ __forceinline__ void rotY(float2 (&re)[16], float2 (&im)[16],
                                     float2 c, float2 s, float2 ns) {
#pragma unroll
    for (int k0 = 0; k0 < 16; k0++) {
        if (k0 & (1 << BQ)) continue;
        const int k1 = k0 | (1 << BQ);
        const float2 r0 = re[k0], r1 = re[k1], i0 = im[k0], i1 = im[k1];
        re[k0] = f2fma(c, r0, f2mul(ns, r1));
        re[k1] = f2fma(s, r0, f2mul(c,  r1));
        im[k0] = f2fma(c, i0, f2mul(ns, i1));
        im[k1] = f2fma(s, i0, f2mul(c,  i1));
    }
}

__global__ void __launch_bounds__(512, 1)
qc_kernel(const float* __restrict__ x, const float* __restrict__ w,
          float* __restrict__ out)
{
    extern __shared__ float4 st[];                 // 8192 x (re-pack, im-pack) = 128 KB
    __shared__ float2 gc[26], gs[26], gns[26];     // RY coeffs, duplicated packed
    __shared__ int    mk9[16];
    __shared__ float2 red[16];

    const int t    = threadIdx.x;
    const int b    = blockIdx.x;                   // batch rows 2b, 2b+1
    const int lane = t & 31;
    const int warp = t >> 5;
    const int cbase = warp << 9;                   // warp-private 512-amp chunk

    if (t < 26) {
        const int l = t / 13, q = t - l * 13;
        const float th = w[l*39 + q*3 + 1];
        float s, c; sincosf(0.5f * th, &s, &c);
        gc[t]  = make_float2( c,  c);
        gs[t]  = make_float2( s,  s);
        gns[t] = make_float2(-s, -s);
    }
    const int ROWS1[13] = ROWS1_INIT;
    if (t < 16) {
        const int i = t << 9;
        int j = 0;
#pragma unroll
        for (int tt = 0; tt < 13; tt++) j |= (__popc(ROWS1[tt] & i) & 1) << tt;
        mk9[t] = j;
    }
    int m0t = 0;
#pragma unroll
    for (int tt = 0; tt < 13; tt++) m0t |= (__popc(ROWS1[tt] & t) & 1) << tt;

    // ---- load two rows (layout A: i = (t<<4)|k), reduce sum-of-squares ----
    float2 re[16], im[16];
    const float4* xp0 = reinterpret_cast<const float4*>(x + (size_t)(2*b)   * DIM + (t << 4));
    const float4* xp1 = reinterpret_cast<const float4*>(x + (size_t)(2*b+1) * DIM + (t << 4));
    float2 ss = make_float2(0.f, 0.f);
#pragma unroll
    for (int k4 = 0; k4 < 4; k4++) {
        const float4 v0 = xp0[k4];
        const float4 v1 = xp1[k4];
        re[k4*4+0] = make_float2(v0.x, v1.x);
        re[k4*4+1] = make_float2(v0.y, v1.y);
        re[k4*4+2] = make_float2(v0.z, v1.z);
        re[k4*4+3] = make_float2(v0.w, v1.w);
    }
#pragma unroll
    for (int k = 0; k < 16; k++) ss = f2fma(re[k], re[k], ss);
#pragma unroll
    for (int o = 16; o > 0; o >>= 1) {
        u64 sv = *(u64*)&ss;
        u64 ov = __shfl_xor_sync(0xffffffffu, sv, o);
        ss = f2add(ss, *(float2*)&ov);
    }
    if (lane == 0) red[warp] = ss;
    __syncthreads();                                             // BAR 1
    float2 tot = make_float2(0.f, 0.f);
#pragma unroll
    for (int r = 0; r < 16; r++) tot = f2add(tot, red[r]);
    const float2 inv = make_float2(rsqrtf(tot.x), rsqrtf(tot.y));

    // ---- A0: per-amp phase on the real normalized input ----
    const float4* t0p = reinterpret_cast<const float4*>(g_t0) + (t << 3);
#pragma unroll
    for (int kk = 0; kk < 8; kk++) {
        const float4 cs = __ldg(&t0p[kk]);
        const int k0 = 2*kk, k1 = 2*kk + 1;
        float2 xs = f2mul(re[k0], inv);
        re[k0] = f2mul(xs, make_float2(cs.x, cs.x));
        im[k0] = f2mul(xs, make_float2(cs.y, cs.y));
        xs = f2mul(re[k1], inv);
        re[k1] = f2mul(xs, make_float2(cs.z, cs.z));
        im[k1] = f2mul(xs, make_float2(cs.w, cs.w));
    }

    // A2-layout addresses (warp-private; also reused for the A2->C write)
    const int a2base = cbase | ((lane & 16) << 4) | (lane & 15);

#pragma unroll 1
    for (int l = 0; l < 2; l++) {
        const int gb = 13 * l;
        // pass A1: reg bits = i bits 0-3 (qubits 12,11,10,9)
        rotY<0>(re, im, gc[gb+12], gs[gb+12], gns[gb+12]);
        rotY<1>(re, im, gc[gb+11], gs[gb+11], gns[gb+11]);
        rotY<2>(re, im, gc[gb+10], gs[gb+10], gns[gb+10]);
        rotY<3>(re, im, gc[gb+ 9], gs[gb+ 9], gns[gb+ 9]);
        // warp-local exchange A1 -> A2 (no block barrier!)
#pragma unroll
        for (int k = 0; k < 16; k++)
            st[phys(cbase | (lane << 4) | k)] = make_float4(re[k].x, re[k].y, im[k].x, im[k].y);
        __syncwarp();
#pragma unroll
        for (int k = 0; k < 16; k++) {
            const float4 v = st[phys(a2base | (k << 4))];
            re[k] = make_float2(v.x, v.y); im[k] = make_float2(v.z, v.w);
        }
        // pass A2: reg bits = i bits 4-7 (qubits 8,7,6,5)
        rotY<0>(re, im, gc[gb+8], gs[gb+8], gns[gb+8]);
        rotY<1>(re, im, gc[gb+7], gs[gb+7], gns[gb+7]);
        rotY<2>(re, im, gc[gb+6], gs[gb+6], gns[gb+6]);
        rotY<3>(re, im, gc[gb+5], gs[gb+5], gns[gb+5]);
        // shfl gate: i bit 8 = lane bit 4 (qubit 4), partner = lane^16
        {
            const float2 cg   = gc[gb + 4];
            const float2 sSel = (lane & 16) ? gs[gb + 4] : gns[gb + 4];
#pragma unroll
            for (int k = 0; k < 16; k++) {
                const u64 pr = __shfl_xor_sync(0xffffffffu, *(u64*)&re[k], 16);
                const u64 pi = __shfl_xor_sync(0xffffffffu, *(u64*)&im[k], 16);
                re[k] = f2fma(cg, re[k], f2mul(sSel, *(const float2*)&pr));
                im[k] = f2fma(cg, im[k], f2mul(sSel, *(const float2*)&pi));
            }
        }
        // A2 -> C block exchange: write own just-read addresses (no pre-barrier)
#pragma unroll
        for (int k = 0; k < 16; k++)
            st[phys(a2base | (k << 4))] = make_float4(re[k].x, re[k].y, im[k].x, im[k].y);
        __syncthreads();                                         // BAR 2 / 5
#pragma unroll
        for (int k = 0; k < 16; k++) {
            const float4 v = st[phys((k << 9) | t)];
            re[k] = make_float2(v.x, v.y); im[k] = make_float2(v.z, v.w);
        }
        // pass C: reg bits = i bits 9-12 (qubits 3,2,1,0)
        rotY<0>(re, im, gc[gb+3], gs[gb+3], gns[gb+3]);
        rotY<1>(re, im, gc[gb+2], gs[gb+2], gns[gb+2]);
        rotY<2>(re, im, gc[gb+1], gs[gb+1], gns[gb+1]);
        rotY<3>(re, im, gc[gb+0], gs[gb+0], gns[gb+0]);

        if (l == 0) {
            // D01 elementwise phase, then layer-0 CNOT permutation as one scatter
            __syncthreads();                                     // BAR 3
#pragma unroll
            for (int k = 0; k < 16; k++) {
                const float2 cs = __ldg(&g_t1[(k << 9) | t]);
                const float2 cd = make_float2(cs.x, cs.x);
                const float2 sd = make_float2(cs.y, cs.y);
                const float2 nsd = make_float2(-cs.y, -cs.y);
                const float2 tr = f2fma(cd, re[k], f2mul(nsd, im[k]));
                const float2 ti = f2fma(sd, re[k], f2mul(cd,  im[k]));
                st[phys(mk9[k] ^ m0t)] = make_float4(tr.x, tr.y, ti.x, ti.y);
            }
            __syncthreads();                                     // BAR 4
#pragma unroll
            for (int k = 0; k < 16; k++) {
                const float4 v = st[phys((t << 4) | k)];
                re[k] = make_float2(v.x, v.y); im[k] = make_float2(v.z, v.w);
            }
        }
    }

    // ---- measurement (layout C): layer-1 CNOT folded into sign mask 5440 ----
    // i = (k<<9)|t: k-mask (bits 12,10) -> 10, t-mask (bits 8,6) -> 320
    const float2 mn1 = make_float2(-1.f, -1.f);
    float2 acc = make_float2(0.f, 0.f);
#pragma unroll
    for (int k = 0; k < 16; k++) {
        const float2 p = f2fma(re[k], re[k], f2mul(im[k], im[k]));
        if (__popc(k & 10) & 1) acc = f2fma(p, mn1, acc);
        else                    acc = f2add(acc, p);
    }
    if (__popc(t & 320) & 1) acc = f2mul(acc, mn1);
#pragma unroll
    for (int o = 16; o > 0; o >>= 1) {
        u64 av = *(u64*)&acc;
        u64 ov = __shfl_xor_sync(0xffffffffu, av, o);
        acc = f2add(acc, *(float2*)&ov);
    }
    if (lane == 0) red[warp] = acc;
    __syncthreads();                                             // BAR 6
    if (t == 0) {
        float2 tt = make_float2(0.f, 0.f);
#pragma unroll
        for (int r = 0; r < 16; r++) tt = f2add(tt, red[r]);
        out[2*b]   = tt.x;
        out[2*b+1] = tt.y;
    }
}

extern "C" void kernel_launch(void* const* d_in, const int* in_sizes, int n_in,
                              void* d_out, int out_size)
{
    const float* x = (const float*)d_in[0];
    const float* w = (const float*)d_in[1];
    float* out = (float*)d_out;
    const int B2 = (in_sizes[0] / DIM) / 2;        // 2 batch rows per CTA

    qc_setup<<<DIM / 256, 256>>>(w);

    const size_t shmem = DIM * sizeof(float4);     // 128 KB
    cudaFuncSetAttribute(qc_kernel, cudaFuncAttributeMaxDynamicSharedMemorySize,
                         (int)shmem);
    qc_kernel<<<B2, 512, shmem>>>(x, w, out);
}

// round 5
// speedup vs baseline: 1.9001x; 1.2843x over previous
#include <cuda_runtime.h>

#define DIM 8192
typedef unsigned long long u64;

// ---- packed f32x2 helpers (SASS FFMA2/FMUL2 path, PTX-only) ----
__device__ __forceinline__ float2 f2fma(float2 a, float2 b, float2 c) {
    u64 r, au = *(u64*)&a, bu = *(u64*)&b, cu = *(u64*)&c;
    asm("fma.rn.f32x2 %0,%1,%2,%3;" : "=l"(r) : "l"(au), "l"(bu), "l"(cu));
    return *(float2*)&r;
}
__device__ __forceinline__ float2 f2mul(float2 a, float2 b) {
    u64 r, au = *(u64*)&a, bu = *(u64*)&b;
    asm("mul.rn.f32x2 %0,%1,%2;" : "=l"(r) : "l"(au), "l"(bu));
    return *(float2*)&r;
}
__device__ __forceinline__ float2 f2add(float2 a, float2 b) {
    u64 r, au = *(u64*)&a, bu = *(u64*)&b;
    asm("add.rn.f32x2 %0,%1,%2;" : "=l"(r) : "l"(au), "l"(bu));
    return *(float2*)&r;
}

// XOR swizzle: conflict-free smem for all structured layouts used below.
__device__ __forceinline__ int phys(int i) {
    return i ^ ((i >> 4) & 15);
}

// Phase tables (shared by all batch rows):
//   g_t0[i]  = layer-0 phi diagonal (applied to the real input)
//   g_t1a    = B0(i)*A1(M0(i)) (layer-0 omega + layer-1 phi conjugated through
//              the layer-0 CNOT map), REARRANGED so the main kernel's gather in
//              layout C' (i = (k<<9)|pt) is a contiguous 128B read per thread.
// All trailing diagonals are unit-modulus under |amp|^2 -> dropped.
__device__ float2 g_t0[DIM];
__device__ float2 g_t1a[DIM];

#define ROWS1_INIT {8191,8190,8188,8184,8176,8160,8128,8064,7936,7680,7168,6144,4095}

__global__ void qc_setup(const float* __restrict__ w) {
    const int i = blockIdx.x * blockDim.x + threadIdx.x;   // 0..8191
    const int ROWS1[13] = ROWS1_INIT;
    float a0 = 0.f, b0 = 0.f;
#pragma unroll
    for (int q = 0; q < 13; q++) {
        const float sgn = ((i >> (12 - q)) & 1) ? 0.5f : -0.5f;
        a0 += sgn * w[q*3 + 0];       // layer-0 phi
        b0 += sgn * w[q*3 + 2];       // layer-0 omega
    }
    int j = 0;
#pragma unroll
    for (int t = 0; t < 13; t++) j |= (__popc(ROWS1[t] & i) & 1) << t;
    float a1 = 0.f;
#pragma unroll
    for (int q = 0; q < 13; q++) {
        const float sgn = ((j >> (12 - q)) & 1) ? 0.5f : -0.5f;
        a1 += sgn * w[39 + q*3 + 0];  // layer-1 phi at M0-permuted index
    }
    float c, s;
    sincosf(a0, &s, &c);      g_t0[i] = make_float2(c, s);
    sincosf(b0 + a1, &s, &c); g_t1a[((i & 511) << 4) | (i >> 9)] = make_float2(c, s);
}

// Plain single-bit real RY rotation on register-bit BQ.
template<int BQ>
__device__ __forceinline__ void rotY(float2 (&re)[16], float2 (&im)[16],
                                     float2 c, float2 s, float2 ns) {
#pragma unroll
    for (int k0 = 0; k0 < 16; k0++) {
        if (k0 & (1 << BQ)) continue;
        const int k1 = k0 | (1 << BQ);
        const float2 r0 = re[k0], r1 = re[k1], i0 = im[k0], i1 = im[k1];
        re[k0] = f2fma(c, r0, f2mul(ns, r1));
        re[k1] = f2fma(s, r0, f2mul(c,  r1));
        im[k0] = f2fma(c, i0, f2mul(ns, i1));
        im[k1] = f2fma(s, i0, f2mul(c,  i1));
    }
}

__global__ void __launch_bounds__(512, 1)
qc_kernel(const float* __restrict__ x, const float* __restrict__ w,
          float* __restrict__ out)
{
    extern __shared__ float4 st[];                 // 8192 x (re-pack, im-pack) = 128 KB
    __shared__ float2 gc[26], gs[26], gns[26];     // RY coeffs, duplicated packed
    __shared__ float2 red[16];

    const int t    = threadIdx.x;
    const int b    = blockIdx.x;                   // batch rows 2b, 2b+1
    const int lane = t & 31;
    const int warp = t >> 5;
    const int cbase = warp << 9;

    if (t < 26) {
        const int l = t / 13, q = t - l * 13;
        const float th = w[l*39 + q*3 + 1];
        float s, c; sincosf(0.5f * th, &s, &c);
        gc[t]  = make_float2( c,  c);
        gs[t]  = make_float2( s,  s);
        gns[t] = make_float2(-s, -s);
    }

    // ---- load two rows (layout A1: i = (t<<4)|k), reduce sum-of-squares ----
    float2 re[16], im[16];
    const float4* xp0 = reinterpret_cast<const float4*>(x + (size_t)(2*b)   * DIM + (t << 4));
    const float4* xp1 = reinterpret_cast<const float4*>(x + (size_t)(2*b+1) * DIM + (t << 4));
    float2 ss = make_float2(0.f, 0.f);
#pragma unroll
    for (int k4 = 0; k4 < 4; k4++) {
        const float4 v0 = xp0[k4];
        const float4 v1 = xp1[k4];
        re[k4*4+0] = make_float2(v0.x, v1.x);
        re[k4*4+1] = make_float2(v0.y, v1.y);
        re[k4*4+2] = make_float2(v0.z, v1.z);
        re[k4*4+3] = make_float2(v0.w, v1.w);
    }
#pragma unroll
    for (int k = 0; k < 16; k++) ss = f2fma(re[k], re[k], ss);
#pragma unroll
    for (int o = 16; o > 0; o >>= 1) {
        u64 sv = *(u64*)&ss;
        u64 ov = __shfl_xor_sync(0xffffffffu, sv, o);
        ss = f2add(ss, *(float2*)&ov);
    }
    if (lane == 0) red[warp] = ss;
    __syncthreads();                                             // BAR 1
    float2 tot = make_float2(0.f, 0.f);
#pragma unroll
    for (int r = 0; r < 16; r++) tot = f2add(tot, red[r]);
    const float2 inv = make_float2(rsqrtf(tot.x), rsqrtf(tot.y));

    // ---- A0: layer-0 phi phase on the real normalized input ----
    const float4* t0p = reinterpret_cast<const float4*>(g_t0) + (t << 3);
#pragma unroll
    for (int kk = 0; kk < 8; kk++) {
        const float4 cs = __ldg(&t0p[kk]);
        const int k0 = 2*kk, k1 = 2*kk + 1;
        float2 xs = f2mul(re[k0], inv);
        re[k0] = f2mul(xs, make_float2(cs.x, cs.x));
        im[k0] = f2mul(xs, make_float2(cs.y, cs.y));
        xs = f2mul(re[k1], inv);
        re[k1] = f2mul(xs, make_float2(cs.z, cs.z));
        im[k1] = f2mul(xs, make_float2(cs.w, cs.w));
    }

    // ==== LAYER 0 (all 13 RY gates) ====
    // pass A1: reg bits = i bits 0-3 (qubits 12..9)
    rotY<0>(re, im, gc[12], gs[12], gns[12]);
    rotY<1>(re, im, gc[11], gs[11], gns[11]);
    rotY<2>(re, im, gc[10], gs[10], gns[10]);
    rotY<3>(re, im, gc[ 9], gs[ 9], gns[ 9]);

    // warp-local exchange A1 -> A2 (reg bits = i bits 4-7)
    const int a2base = cbase | ((lane & 16) << 4) | (lane & 15);
#pragma unroll
    for (int k = 0; k < 16; k++)
        st[phys(cbase | (lane << 4) | k)] = make_float4(re[k].x, re[k].y, im[k].x, im[k].y);
    __syncwarp();
#pragma unroll
    for (int k = 0; k < 16; k++) {
        const float4 v = st[phys(a2base | (k << 4))];
        re[k] = make_float2(v.x, v.y); im[k] = make_float2(v.z, v.w);
    }
    rotY<0>(re, im, gc[8], gs[8], gns[8]);
    rotY<1>(re, im, gc[7], gs[7], gns[7]);
    rotY<2>(re, im, gc[6], gs[6], gns[6]);
    rotY<3>(re, im, gc[5], gs[5], gns[5]);
    // shfl gate on i bit 8 (= lane bit 4), qubit 4
    {
        const float2 cg   = gc[4];
        const float2 sSel = (lane & 16) ? gs[4] : gns[4];
#pragma unroll
        for (int k = 0; k < 16; k++) {
            const u64 pr = __shfl_xor_sync(0xffffffffu, *(u64*)&re[k], 16);
            const u64 pi = __shfl_xor_sync(0xffffffffu, *(u64*)&im[k], 16);
            re[k] = f2fma(cg, re[k], f2mul(sSel, *(const float2*)&pr));
            im[k] = f2fma(cg, im[k], f2mul(sSel, *(const float2*)&pi));
        }
    }

    // block exchange A2 -> C' : i = (k<<9) | pt, pt = (lane<<4) | warp
#pragma unroll
    for (int k = 0; k < 16; k++)
        st[phys(a2base | (k << 4))] = make_float4(re[k].x, re[k].y, im[k].x, im[k].y);
    __syncthreads();                                             // BAR 2
    const int pt = (lane << 4) | warp;
#pragma unroll
    for (int k = 0; k < 16; k++) {
        const float4 v = st[phys((k << 9) | pt)];
        re[k] = make_float2(v.x, v.y); im[k] = make_float2(v.z, v.w);
    }
    // pass C': reg bits = i bits 9-12 (qubits 3..0)
    rotY<0>(re, im, gc[3], gs[3], gns[3]);
    rotY<1>(re, im, gc[2], gs[2], gns[2]);
    rotY<2>(re, im, gc[1], gs[1], gns[1]);
    rotY<3>(re, im, gc[0], gs[0], gns[0]);

    // ==== D01 diagonal (layer-0 omega + layer-1 phi @ M0(i)) ====
    const float4* t1p = reinterpret_cast<const float4*>(g_t1a) + (pt << 3);
#pragma unroll
    for (int kk = 0; kk < 8; kk++) {
        const float4 cs = __ldg(&t1p[kk]);
        {
            const int k0 = 2*kk;
            const float2 cd = make_float2(cs.x, cs.x);
            const float2 sd = make_float2(cs.y, cs.y);
            const float2 nd = make_float2(-cs.y, -cs.y);
            const float2 tr = f2fma(cd, re[k0], f2mul(nd, im[k0]));
            const float2 ti = f2fma(sd, re[k0], f2mul(cd, im[k0]));
            re[k0] = tr; im[k0] = ti;
        }
        {
            const int k1 = 2*kk + 1;
            const float2 cd = make_float2(cs.z, cs.z);
            const float2 sd = make_float2(cs.w, cs.w);
            const float2 nd = make_float2(-cs.w, -cs.w);
            const float2 tr = f2fma(cd, re[k1], f2mul(nd, im[k1]));
            const float2 ti = f2fma(sd, re[k1], f2mul(cd, im[k1]));
            re[k1] = tr; im[k1] = ti;
        }
    }

    // ==== LAYER 1: only the 4 observable-relevant gates, conjugated by M0 ====
    // d12 = {11,12} (k-mask 12), orient = parity(i & 4095) : gate gc[13] (qubit 0)
    {
        const int Pt = __popc(pt) & 1;
        const float2 c = gc[13];
#pragma unroll
        for (int k0 = 0; k0 < 8; k0++) {           // k0 bit3 == 0
            const int k1 = k0 ^ 12;
            const int o = Pt ^ (__popc(k0 & 7) & 1);
            const float2 sa = o ? gs[13] : gns[13];   // coef of b in a'
            const float2 sb = o ? gns[13] : gs[13];   // coef of a in b'
            const float2 ar = re[k0], ai = im[k0], br = re[k1], bi = im[k1];
            re[k0] = f2fma(c, ar, f2mul(sa, br));
            im[k0] = f2fma(c, ai, f2mul(sa, bi));
            re[k1] = f2fma(c, br, f2mul(sb, ar));
            im[k1] = f2fma(c, bi, f2mul(sb, ai));
        }
    }
    // d10 = {9,10} (k-mask 3), orient = parity(k & 14) : gate gc[15] (qubit 2)
    {
        const float2 c = gc[15];
#pragma unroll
        for (int k0 = 0; k0 < 16; k0++) {
            if ((k0 & 3) > 1) continue;             // k0&3 in {0,1}
            const int k1 = k0 ^ 3;
            const int o = __popc(k0 & 14) & 1;      // compile-time
            const float2 sa = o ? gs[15] : gns[15];
            const float2 sb = o ? gns[15] : gs[15];
            const float2 ar = re[k0], ai = im[k0], br = re[k1], bi = im[k1];
            re[k0] = f2fma(c, ar, f2mul(sa, br));
            im[k0] = f2fma(c, ai, f2mul(sa, bi));
            re[k1] = f2fma(c, br, f2mul(sb, ar));
            im[k1] = f2fma(c, bi, f2mul(sb, ai));
        }
    }
    // d8 = {7,8} (lane-mask 24, shfl), orient = lane bit4 ^ parity(k) : gc[17] (qubit 4)
    {
        const float2 c = gc[17];
        const int oL = (lane >> 4) & 1;
        const float2 sEv = oL ? gs[17] : gns[17];
        const float2 sOd = oL ? gns[17] : gs[17];
#pragma unroll
        for (int k = 0; k < 16; k++) {
            const u64 pr = __shfl_xor_sync(0xffffffffu, *(u64*)&re[k], 24);
            const u64 pi = __shfl_xor_sync(0xffffffffu, *(u64*)&im[k], 24);
            const float2 sc = (__popc(k) & 1) ? sOd : sEv;
            re[k] = f2fma(c, re[k], f2mul(sc, *(const float2*)&pr));
            im[k] = f2fma(c, im[k], f2mul(sc, *(const float2*)&pi));
        }
    }
    // d6 = {5,6} (lane-mask 6, shfl), orient = parity(lane&28) ^ parity(k) : gc[19] (qubit 6)
    {
        const float2 c = gc[19];
        const int oL = __popc(lane & 28) & 1;
        const float2 sEv = oL ? gs[19] : gns[19];
        const float2 sOd = oL ? gns[19] : gs[19];
#pragma unroll
        for (int k = 0; k < 16; k++) {
            const u64 pr = __shfl_xor_sync(0xffffffffu, *(u64*)&re[k], 6);
            const u64 pi = __shfl_xor_sync(0xffffffffu, *(u64*)&im[k], 6);
            const float2 sc = (__popc(k) & 1) ? sOd : sEv;
            re[k] = f2fma(c, re[k], f2mul(sc, *(const float2*)&pr));
            im[k] = f2fma(c, im[k], f2mul(sc, *(const float2*)&pi));
        }
    }

    // ==== measurement: sign = parity(i & 4927) in i-space ====
    // thread part: lane-mask 19 ^ warp parity; k part: k-mask 9
    const float2 mn1 = make_float2(-1.f, -1.f);
    const int sgt = (__popc(lane & 19) + __popc(warp)) & 1;
    float2 acc = make_float2(0.f, 0.f);
#pragma unroll
    for (int k = 0; k < 16; k++) {
        const float2 p = f2fma(re[k], re[k], f2mul(im[k], im[k]));
        if (__popc(k & 9) & 1) acc = f2fma(p, mn1, acc);
        else                   acc = f2add(acc, p);
    }
    if (sgt) acc = f2mul(acc, mn1);
#pragma unroll
    for (int o = 16; o > 0; o >>= 1) {
        u64 av = *(u64*)&acc;
        u64 ov = __shfl_xor_sync(0xffffffffu, av, o);
        acc = f2add(acc, *(float2*)&ov);
    }
    if (lane == 0) red[warp] = acc;
    __syncthreads();                                             // BAR 3
    if (t == 0) {
        float2 tt = make_float2(0.f, 0.f);
#pragma unroll
        for (int r = 0; r < 16; r++) tt = f2add(tt, red[r]);
        out[2*b]   = tt.x;
        out[2*b+1] = tt.y;
    }
}

extern "C" void kernel_launch(void* const* d_in, const int* in_sizes, int n_in,
                              void* d_out, int out_size)
{
    const float* x = (const float*)d_in[0];
    const float* w = (const float*)d_in[1];
    float* out = (float*)d_out;
    const int B2 = (in_sizes[0] / DIM) / 2;        // 2 batch rows per CTA

    qc_setup<<<DIM / 256, 256>>>(w);

    const size_t shmem = DIM * sizeof(float4);     // 128 KB
    cudaFuncSetAttribute(qc_kernel, cudaFuncAttributeMaxDynamicSharedMemorySize,
                         (int)shmem);
    qc_kernel<<<B2, 512, shmem>>>(x, w, out);
}